// round 7
// baseline (speedup 1.0000x reference)
#include <cuda_runtime.h>
#include <cuda_bf16.h>
#include <math.h>
#include <stdint.h>

#define TT   128
#define BB   512
#define DD   512
#define MM   6
#define JJ   (TT + MM)
#define HH   2
#define DFF  64
#define ACT  64
#define NROW (TT * BB)
#define JROW (JJ * BB)
#define BG   0.1f

typedef __nv_bfloat16 bf16;

// ---------- static scratch ----------
__device__ __align__(256) float g_B1[NROW * DD];
__device__ __align__(256) float g_B4[NROW * DD];
__device__ __align__(256) float g_kv [JROW * 128];
__device__ __align__(256) float g_q  [NROW * 64];
__device__ __align__(256) float g_p  [JJ * 64];
__device__ __align__(256) float g_ts [BB * DD];
__device__ __align__(256) float g_h1 [BB * 1024];
__device__ __align__(256) float g_h2 [BB * 512];
__device__ __align__(256) float g_h3 [BB * 300];
__device__ __align__(256) bf16 gb_x  [NROW * DD];
__device__ __align__(256) bf16 gb_ln [NROW * DD];
__device__ __align__(256) bf16 gb_y  [NROW * DD];
__device__ __align__(256) bf16 gb_rx [NROW * DD];
__device__ __align__(256) bf16 gb_z  [NROW * DD];
__device__ __align__(256) bf16 gb_src[NROW * DD];
__device__ __align__(256) bf16 gb_ffh[NROW * DFF];
__device__ __align__(256) bf16 gb_av [NROW * 64];
__device__ __align__(256) bf16 gb_mem[MM * BB * DD];
__device__ __align__(256) bf16 gb_wq  [64 * DD];
__device__ __align__(256) bf16 gb_wkv [128 * DD];
__device__ __align__(256) bf16 gb_wout[DD * 64];
__device__ __align__(256) bf16 gb_g1  [6 * DD * DD];
__device__ __align__(256) bf16 gb_g2  [6 * DD * DD];
__device__ __align__(256) bf16 gb_ff1 [DFF * DD];
__device__ __align__(256) bf16 gb_ff2 [DD * DFF];

// ---------- helpers ----------
__device__ __forceinline__ uint32_t s2u(const void* p) {
    return (uint32_t)__cvta_generic_to_shared(p);
}
__device__ __forceinline__ void cp16(uint32_t s, const void* g) {
    asm volatile("cp.async.cg.shared.global [%0], [%1], 16;" :: "r"(s), "l"(g));
}
__device__ __forceinline__ void cp_commit() { asm volatile("cp.async.commit_group;" ::: "memory"); }
__device__ __forceinline__ void cp_wait0()  { asm volatile("cp.async.wait_group 0;" ::: "memory"); }
__device__ __forceinline__ void cp_wait1()  { asm volatile("cp.async.wait_group 1;" ::: "memory"); }
__device__ __forceinline__ void ldsm4(uint32_t* r, uint32_t addr) {
    asm volatile("ldmatrix.sync.aligned.m8n8.x4.shared.b16 {%0,%1,%2,%3}, [%4];"
                 : "=r"(r[0]), "=r"(r[1]), "=r"(r[2]), "=r"(r[3]) : "r"(addr));
}
__device__ __forceinline__ void mma_bf16(float* c, const uint32_t* a, const uint32_t* b) {
    asm volatile(
        "mma.sync.aligned.m16n8k16.row.col.f32.bf16.bf16.f32 "
        "{%0,%1,%2,%3}, {%4,%5,%6,%7}, {%8,%9}, {%0,%1,%2,%3};"
        : "+f"(c[0]), "+f"(c[1]), "+f"(c[2]), "+f"(c[3])
        : "r"(a[0]), "r"(a[1]), "r"(a[2]), "r"(a[3]), "r"(b[0]), "r"(b[1]));
}

// ---------- bf16 dual-source tensor GEMM (ldmatrix + 3-stage cp.async) ----------
// C[M,N] = A0[M,K0]@W0[N,K0]^T + A1[M,K1]@W1[N,K1]^T (+bias1+bias2+cadd)
// modes: 0 f32 | 2 bf16 | 3 bf16 relu | 4 bf16 = sigmoid(v)*aux
//        5 f32(+opt bf16) = (1-sig(zpre))*aux + sig(zpre)*tanh(v)
// If W0z != null: grid.x is doubled; upper-half CTAs compute the "z" GEMM
// (same A pair, weights W0z/W1z, biases b1z/b2z, cadd=-BG, mode2 -> Cz).
// Requirements: M%128==0, N%NT==0, K0,K1 % 64 == 0.

template<int NT>
__global__ __launch_bounds__(256, (NT >= 256 ? 1 : 2))
void bgemm(const bf16* __restrict__ A0, const bf16* W0, int K0,
           const bf16* __restrict__ A1, const bf16* W1, int K1,
           int N,
           float* __restrict__ Cf, bf16* Cb,
           const float* bias1, const float* bias2,
           float cadd, const bf16* __restrict__ zpre, const float* __restrict__ aux,
           int mode,
           const bf16* W0z, const bf16* W1z,
           const float* b1z, const float* b2z, bf16* Cz)
{
    extern __shared__ char dsm[];
    constexpr int NTI = NT / 32;
    constexpr int STG = (128 + NT) * 144;

    const int tid  = threadIdx.x;
    const int warp = tid >> 5, lane = tid & 31;
    const int grp  = lane >> 2, thr = lane & 3;
    const int wm   = warp & 1,  wn  = warp >> 1;
    const int m_base = wm * 64;
    const int n_base = wn * (NT / 4);
    const int row0 = blockIdx.y * 128;
    int col0 = blockIdx.x * NT;
    const uint32_t sb = s2u(dsm);

    if (W0z && col0 >= N) {
        col0 -= N;
        W0 = W0z; W1 = W1z; bias1 = b1z; bias2 = b2z;
        cadd = -BG; mode = 2; Cb = Cz;
    }

    float acc[4][NTI][4];
#pragma unroll
    for (int i = 0; i < 4; i++)
#pragma unroll
        for (int j = 0; j < NTI; j++)
#pragma unroll
            for (int r = 0; r < 4; r++) acc[i][j][r] = 0.f;

    const int NC0 = K0 >> 6;
    const int NC  = NC0 + (K1 >> 6);

    auto load_stage = [&](int c, int buf) {
        const bf16 *a, *w; int k, kb;
        if (c < NC0) { a = A0; w = W0; k = K0; kb = c << 6; }
        else         { a = A1; w = W1; k = K1; kb = (c - NC0) << 6; }
        uint32_t ab = sb + (uint32_t)buf * STG;
#pragma unroll
        for (int i = 0; i < 4; i++) {
            int u = tid + i * 256;
            int r = u >> 3, cc = u & 7;
            cp16(ab + (uint32_t)(r * 144 + cc * 16),
                 a + (size_t)(row0 + r) * k + kb + cc * 8);
        }
        uint32_t bb = ab + 128u * 144u;
#pragma unroll
        for (int i = 0; i < NT / 32; i++) {
            int u = tid + i * 256;
            int r = u >> 3, cc = u & 7;
            cp16(bb + (uint32_t)(r * 144 + cc * 16),
                 w + (size_t)(col0 + r) * k + kb + cc * 8);
        }
        cp_commit();
    };

    load_stage(0, 0);
    if (NC > 1) load_stage(1, 1);

    for (int c = 0; c < NC; c++) {
        if (c == NC - 1) cp_wait0(); else cp_wait1();
        __syncthreads();
        if (c + 2 < NC) load_stage(c + 2, (c + 2) % 3);

        uint32_t ab = sb + (uint32_t)(c % 3) * STG;
        uint32_t bb = ab + 128u * 144u;

        const uint32_t a_lrow = (uint32_t)(lane & 15);
        const uint32_t a_koff = (uint32_t)((lane >> 4) << 3);
        const uint32_t b_cofs = (uint32_t)(((lane >> 4) << 3) + (lane & 7));
        const uint32_t b_koff = (uint32_t)(((lane >> 3) & 1) << 3);

#pragma unroll
        for (int ks = 0; ks < 4; ks++) {
            const int kc = ks * 16;
            uint32_t af[4][4], bfr[NTI][2];
#pragma unroll
            for (int mt = 0; mt < 4; mt++) {
                uint32_t addr = ab + (uint32_t)(m_base + mt * 16 + a_lrow) * 144u
                                   + (uint32_t)(kc + a_koff) * 2u;
                ldsm4(af[mt], addr);
            }
#pragma unroll
            for (int p = 0; p < NTI / 2; p++) {
                uint32_t col = (uint32_t)(n_base + p * 16) + b_cofs;
                uint32_t addr = bb + col * 144u + (uint32_t)(kc + b_koff) * 2u;
                uint32_t r[4];
                ldsm4(r, addr);
                bfr[2 * p][0]     = r[0]; bfr[2 * p][1]     = r[1];
                bfr[2 * p + 1][0] = r[2]; bfr[2 * p + 1][1] = r[3];
            }
#pragma unroll
            for (int mt = 0; mt < 4; mt++)
#pragma unroll
                for (int nt = 0; nt < NTI; nt++)
                    mma_bf16(acc[mt][nt], af[mt], bfr[nt]);
        }
    }

    // epilogue
#pragma unroll
    for (int mt = 0; mt < 4; mt++) {
#pragma unroll
        for (int nt = 0; nt < NTI; nt++) {
            int cbase = col0 + n_base + nt * 8 + thr * 2;
            float b0 = cadd, b1 = cadd;
            if (bias1) { b0 += bias1[cbase]; b1 += bias1[cbase + 1]; }
            if (bias2) { b0 += bias2[cbase]; b1 += bias2[cbase + 1]; }
#pragma unroll
            for (int half = 0; half < 2; half++) {
                int r = row0 + m_base + mt * 16 + grp + half * 8;
                size_t idx0 = (size_t)r * N + cbase;
#pragma unroll
                for (int e = 0; e < 2; e++) {
                    float v = acc[mt][nt][half * 2 + e] + (e ? b1 : b0);
                    size_t idx = idx0 + e;
                    if (mode == 0) {
                        Cf[idx] = v;
                    } else if (mode == 2) {
                        Cb[idx] = __float2bfloat16(v);
                    } else if (mode == 3) {
                        Cb[idx] = __float2bfloat16(fmaxf(v, 0.f));
                    } else if (mode == 4) {
                        float s = 1.f / (1.f + __expf(-v));
                        Cb[idx] = __float2bfloat16(s * aux[idx]);
                    } else {
                        float z = 1.f / (1.f + __expf(-__bfloat162float(zpre[idx])));
                        float o = (1.f - z) * aux[idx] + z * tanhf(v);
                        Cf[idx] = o;
                        if (Cb) Cb[idx] = __float2bfloat16(o);
                    }
                }
            }
        }
    }
}

// ---------- exact fp32 GEMM, 64x64 tiles (critic head) ----------
__global__ void sgemm64_kernel(const float* __restrict__ A, const float* __restrict__ W,
                               float* __restrict__ C, int M, int N, int K,
                               const float* __restrict__ bias, float cadd, int flags)
{
    __shared__ float As[8][64];
    __shared__ float Bs[8][65];
    int tid = threadIdx.x;
    int row0 = blockIdx.y * 64, col0 = blockIdx.x * 64;
    int tx = tid & 15, ty = tid >> 4;
    float acc[4][4];
#pragma unroll
    for (int i = 0; i < 4; i++)
#pragma unroll
        for (int j = 0; j < 4; j++) acc[i][j] = 0.f;

    int ar = tid >> 2, ac2 = (tid & 3) * 2;
    int br = tid >> 5, bc = tid & 31;

    for (int k0 = 0; k0 < K; k0 += 8) {
        float2 a2 = *reinterpret_cast<const float2*>(A + (size_t)(row0 + ar) * K + k0 + ac2);
        As[ac2][ar] = a2.x;
        As[ac2 + 1][ar] = a2.y;
        float w0 = (col0 + bc < N)      ? W[(size_t)(k0 + br) * N + col0 + bc]      : 0.f;
        float w1 = (col0 + bc + 32 < N) ? W[(size_t)(k0 + br) * N + col0 + bc + 32] : 0.f;
        Bs[br][bc] = w0;
        Bs[br][bc + 32] = w1;
        __syncthreads();
#pragma unroll
        for (int kk = 0; kk < 8; kk++) {
            float av[4], bv[4];
#pragma unroll
            for (int i = 0; i < 4; i++) av[i] = As[kk][ty * 4 + i];
#pragma unroll
            for (int j = 0; j < 4; j++) bv[j] = Bs[kk][tx * 4 + j];
#pragma unroll
            for (int i = 0; i < 4; i++)
#pragma unroll
                for (int j = 0; j < 4; j++) acc[i][j] += av[i] * bv[j];
        }
        __syncthreads();
    }
#pragma unroll
    for (int i = 0; i < 4; i++) {
        int r = row0 + ty * 4 + i;
        if (r >= M) continue;
#pragma unroll
        for (int j = 0; j < 4; j++) {
            int c = col0 + tx * 4 + j;
            if (c >= N) continue;
            float val = acc[i][j] + cadd;
            if (bias) val += bias[c];
            size_t idx = (size_t)r * N + c;
            if (flags & 1) val += C[idx];
            if (flags & 2) val = fmaxf(val, 0.f);
            C[idx] = val;
        }
    }
}

// ---------- LayerNorm (bf16 out) ----------
__global__ void ln_kernel(const float* __restrict__ x, bf16* __restrict__ out,
                          const float* __restrict__ g, const float* __restrict__ b, int rows)
{
    int warp = blockIdx.x * (blockDim.x >> 5) + (threadIdx.x >> 5);
    if (warp >= rows) return;
    int lane = threadIdx.x & 31;
    const float* xr = x + (size_t)warp * DD;
    float v[16], s1 = 0.f, s2 = 0.f;
#pragma unroll
    for (int i = 0; i < 16; i++) {
        float t = xr[i * 32 + lane];
        v[i] = t; s1 += t; s2 += t * t;
    }
#pragma unroll
    for (int o = 16; o; o >>= 1) {
        s1 += __shfl_xor_sync(0xffffffffu, s1, o);
        s2 += __shfl_xor_sync(0xffffffffu, s2, o);
    }
    float mu = s1 * (1.f / DD);
    float inv = rsqrtf(s2 * (1.f / DD) - mu * mu + 1e-5f);
    bf16* orow = out + (size_t)warp * DD;
#pragma unroll
    for (int i = 0; i < 16; i++) {
        int d = i * 32 + lane;
        orow[d] = __float2bfloat16((v[i] - mu) * inv * g[d] + b[d]);
    }
}

// ---------- pos-emb @ W_p ----------
__global__ void prep_p_kernel(const float* __restrict__ Wp, float* __restrict__ p)
{
    int jj = blockIdx.x;
    __shared__ float pe[DD];
    float pos = (float)(JJ - 1 - jj);
    for (int d = threadIdx.x; d < DD; d += 64) {
        int i = (d < 256) ? d : d - 256;
        float f = __expf(-(float)(2 * i) * (1.f / 512.f) * 9.210340371976184f);
        float a = pos * f;
        pe[d] = (d < 256) ? sinf(a) : cosf(a);
    }
    __syncthreads();
    int c = threadIdx.x;
    float acc = 0.f;
    for (int d = 0; d < DD; d++) acc += pe[d] * Wp[d * 64 + c];
    p[jj * 64 + c] = acc;
}

// ---------- attention (bf16 av out) ----------
__global__ void attn_kernel(const float* __restrict__ q, const float* __restrict__ kv,
                            const float* __restrict__ p, const float* __restrict__ uu,
                            const float* __restrict__ vvec, bf16* __restrict__ av)
{
    int b = blockIdx.x, h = blockIdx.y;
    __shared__ float Ks[JJ][33];
    __shared__ float Vs[JJ][33];
    __shared__ float att[4][JJ];
    __shared__ float qsu[4][32];
    __shared__ float qsv[4][32];
    int tid = threadIdx.x;
    for (int idx = tid; idx < JJ * 32; idx += 128) {
        int j = idx >> 5, d = idx & 31;
        const float* row = kv + ((size_t)j * BB + b) * 128 + h * 32 + d;
        Ks[j][d] = row[0];
        Vs[j][d] = row[64];
    }
    __syncthreads();
    int warp = tid >> 5, lane = tid & 31;
    float ul = uu[h * 32 + lane], vl = vvec[h * 32 + lane];
    for (int i = warp; i < TT; i += 4) {
        float qv = q[((size_t)i * BB + b) * 64 + h * 32 + lane];
        qsu[warp][lane] = qv + ul;
        qsv[warp][lane] = qv + vl;
        __syncwarp();
        int jmax = i + MM;
        float sv[5], smax = -1e30f;
        int cnt = 0;
        for (int j = lane; j <= jmax; j += 32) {
            const float* prow = p + (size_t)(j + TT - 1 - i) * 64 + h * 32;
            float s = 0.f;
#pragma unroll
            for (int d = 0; d < 32; d++)
                s += qsu[warp][d] * Ks[j][d] + qsv[warp][d] * prow[d];
            s *= 0.1767766952966369f;
            sv[cnt++] = s;
            smax = fmaxf(smax, s);
        }
#pragma unroll
        for (int o = 16; o; o >>= 1) smax = fmaxf(smax, __shfl_xor_sync(0xffffffffu, smax, o));
        float sum = 0.f; cnt = 0;
        for (int j = lane; j <= jmax; j += 32) {
            float e = __expf(sv[cnt++] - smax);
            att[warp][j] = e;
            sum += e;
        }
#pragma unroll
        for (int o = 16; o; o >>= 1) sum += __shfl_xor_sync(0xffffffffu, sum, o);
        float inv = 1.f / sum;
        __syncwarp();
        float acc = 0.f;
        for (int j = 0; j <= jmax; j++) acc += att[warp][j] * Vs[j][lane];
        av[((size_t)i * BB + b) * 64 + h * 32 + lane] = __float2bfloat16(acc * inv);
        __syncwarp();
    }
}

// ---------- transpose+convert W[K,N] f32 -> [N,K] bf16 ----------
__global__ void tpose_kernel(const float* __restrict__ in, bf16* __restrict__ out, int K, int N)
{
    __shared__ float t[32][33];
    int k0 = blockIdx.y * 32, n0 = blockIdx.x * 32;
    int x = threadIdx.x, y = threadIdx.y;
    for (int i = y; i < 32; i += 8)
        t[i][x] = in[(size_t)(k0 + i) * N + n0 + x];
    __syncthreads();
    for (int i = y; i < 32; i += 8)
        out[(size_t)(n0 + i) * K + k0 + x] = __float2bfloat16(t[x][i]);
}

// ---------- batched transpose for the 12 gate matrices (512x512) ----------
__global__ void btpose_kernel(const float* __restrict__ g1, const float* __restrict__ g2,
                              bf16* __restrict__ o1, bf16* __restrict__ o2)
{
    __shared__ float t[32][33];
    int z = blockIdx.z;
    const float* in = (z < 6) ? (g1 + (size_t)z * DD * DD) : (g2 + (size_t)(z - 6) * DD * DD);
    bf16* out = (z < 6) ? (o1 + (size_t)z * DD * DD) : (o2 + (size_t)(z - 6) * DD * DD);
    int k0 = blockIdx.y * 32, n0 = blockIdx.x * 32;
    int x = threadIdx.x, y = threadIdx.y;
    for (int i = y; i < 32; i += 8)
        t[i][x] = in[(size_t)(k0 + i) * DD + n0 + x];
    __syncthreads();
    for (int i = y; i < 32; i += 8)
        out[(size_t)(n0 + i) * DD + k0 + x] = __float2bfloat16(t[x][i]);
}

// ---------- f32 -> bf16 ----------
__global__ void cvt_kernel(const float* __restrict__ in, bf16* __restrict__ out, int n4)
{
    int i = blockIdx.x * blockDim.x + threadIdx.x;
    if (i >= n4) return;
    float4 v = reinterpret_cast<const float4*>(in)[i];
    __nv_bfloat162* o = reinterpret_cast<__nv_bfloat162*>(out + (size_t)i * 4);
    o[0] = __floats2bfloat162_rn(v.x, v.y);
    o[1] = __floats2bfloat162_rn(v.z, v.w);
}

// ---------- mean pool (vectorized) ----------
__global__ void meanpool_kernel(const float4* __restrict__ in, float4* __restrict__ ts)
{
    int idx = blockIdx.x * blockDim.x + threadIdx.x;
    const int n4 = BB * DD / 4;
    if (idx >= n4) return;
    float4 s = make_float4(0.f, 0.f, 0.f, 0.f);
    for (int t = 0; t < TT; t++) {
        float4 v = in[(size_t)t * n4 + idx];
        s.x += v.x; s.y += v.y; s.z += v.z; s.w += v.w;
    }
    const float inv = 1.f / TT;
    s.x *= inv; s.y *= inv; s.z *= inv; s.w *= inv;
    ts[idx] = s;
}

// ---------- final head ----------
__global__ void final_kernel(const float* __restrict__ h3, const float* __restrict__ w,
                             const float* __restrict__ bb, float* __restrict__ out)
{
    int row = blockIdx.x * 4 + (threadIdx.x >> 5);
    int lane = threadIdx.x & 31;
    if (row >= BB) return;
    float s = 0.f;
    for (int k = lane; k < 300; k += 32) s += h3[(size_t)row * 300 + k] * w[k];
#pragma unroll
    for (int o = 16; o; o >>= 1) s += __shfl_xor_sync(0xffffffffu, s, o);
    if (lane == 0) out[row] = fmaxf(s + bb[0], 0.f);
}

// ---------- host ----------
static inline void launch_tc(const bf16* A0, const bf16* W0, int K0,
                             const bf16* A1, const bf16* W1, int K1,
                             int M, int N, int NT,
                             float* Cf, bf16* Cb,
                             const float* b1, const float* b2, float cadd,
                             const bf16* zpre, const float* aux, int mode,
                             const bf16* W0z = 0, const bf16* W1z = 0,
                             const float* b1z = 0, const float* b2z = 0, bf16* Cz = 0)
{
    int gx = (W0z ? 2 * N : N) / NT;
    dim3 grid(gx, M / 128);
    if (NT == 256) {
        size_t dsz = 3 * (size_t)(128 + 256) * 144;
        bgemm<256><<<grid, 256, dsz>>>(A0, W0, K0, A1, W1, K1, N, Cf, Cb, b1, b2, cadd,
                                       zpre, aux, mode, W0z, W1z, b1z, b2z, Cz);
    } else if (NT == 128) {
        size_t dsz = 3 * (size_t)(128 + 128) * 144;
        bgemm<128><<<grid, 256, dsz>>>(A0, W0, K0, A1, W1, K1, N, Cf, Cb, b1, b2, cadd,
                                       zpre, aux, mode, W0z, W1z, b1z, b2z, Cz);
    } else {
        size_t dsz = 3 * (size_t)(128 + 64) * 144;
        bgemm<64><<<grid, 256, dsz>>>(A0, W0, K0, A1, W1, K1, N, Cf, Cb, b1, b2, cadd,
                                      zpre, aux, mode, W0z, W1z, b1z, b2z, Cz);
    }
}
static inline void launch_sgemm(const float* A, const float* W, float* C,
                                int M, int N, int K, const float* bias, float cadd, int flags)
{
    dim3 grid((N + 63) / 64, (M + 63) / 64);
    sgemm64_kernel<<<grid, 256>>>(A, W, C, M, N, K, bias, cadd, flags);
}
static inline void launch_tpose(const float* in, bf16* out, int K, int N)
{
    tpose_kernel<<<dim3(N / 32, K / 32), dim3(32, 8)>>>(in, out, K, N);
}

extern "C" void kernel_launch(void* const* d_in, const int* in_sizes, int n_in,
                              void* d_out, int out_size)
{
    const float* x      = (const float*)d_in[0];
    const float* action = (const float*)d_in[1];
    const float* memory = (const float*)d_in[2];
    const float* W_q    = (const float*)d_in[3];
    const float* W_kv   = (const float*)d_in[4];
    const float* W_p    = (const float*)d_in[5];
    const float* W_out  = (const float*)d_in[6];
    const float* u      = (const float*)d_in[7];
    const float* v      = (const float*)d_in[8];
    const float* ln1_g  = (const float*)d_in[9];
    const float* ln1_b  = (const float*)d_in[10];
    const float* ln2_g  = (const float*)d_in[11];
    const float* ln2_b  = (const float*)d_in[12];
    const float* ff_W1  = (const float*)d_in[13];
    const float* ff_b1  = (const float*)d_in[14];
    const float* ff_W2  = (const float*)d_in[15];
    const float* ff_b2  = (const float*)d_in[16];
    const float* g1W    = (const float*)d_in[17];
    const float* g1b    = (const float*)d_in[18];
    const float* g2W    = (const float*)d_in[19];
    const float* g2b    = (const float*)d_in[20];
    const float* d1W    = (const float*)d_in[21];
    const float* d1b    = (const float*)d_in[22];
    const float* d2W    = (const float*)d_in[23];
    const float* d2b    = (const float*)d_in[24];
    const float* d3W    = (const float*)d_in[25];
    const float* d3b    = (const float*)d_in[26];
    const float* d4W    = (const float*)d_in[27];
    const float* d4b    = (const float*)d_in[28];

    cudaFuncSetAttribute(bgemm<256>, cudaFuncAttributeMaxDynamicSharedMemorySize, 166000);
    cudaFuncSetAttribute(bgemm<128>, cudaFuncAttributeMaxDynamicSharedMemorySize, 111000);
    cudaFuncSetAttribute(bgemm<64>,  cudaFuncAttributeMaxDynamicSharedMemorySize, 84000);

    float *B1, *B4, *KV, *Q, *P, *TS, *H1, *H2, *H3;
    bf16 *XB, *LNB, *YB, *RXB, *ZB, *SRCB, *FFHB, *AVB, *MEMB;
    bf16 *WQT, *WKVT, *WOUTT, *G1T, *G2T, *FF1T, *FF2T;
    cudaGetSymbolAddress((void**)&B1,   g_B1);
    cudaGetSymbolAddress((void**)&B4,   g_B4);
    cudaGetSymbolAddress((void**)&KV,   g_kv);
    cudaGetSymbolAddress((void**)&Q,    g_q);
    cudaGetSymbolAddress((void**)&P,    g_p);
    cudaGetSymbolAddress((void**)&TS,   g_ts);
    cudaGetSymbolAddress((void**)&H1,   g_h1);
    cudaGetSymbolAddress((void**)&H2,   g_h2);
    cudaGetSymbolAddress((void**)&H3,   g_h3);
    cudaGetSymbolAddress((void**)&XB,   gb_x);
    cudaGetSymbolAddress((void**)&LNB,  gb_ln);
    cudaGetSymbolAddress((void**)&YB,   gb_y);
    cudaGetSymbolAddress((void**)&RXB,  gb_rx);
    cudaGetSymbolAddress((void**)&ZB,   gb_z);
    cudaGetSymbolAddress((void**)&SRCB, gb_src);
    cudaGetSymbolAddress((void**)&FFHB, gb_ffh);
    cudaGetSymbolAddress((void**)&AVB,  gb_av);
    cudaGetSymbolAddress((void**)&MEMB, gb_mem);
    cudaGetSymbolAddress((void**)&WQT,  gb_wq);
    cudaGetSymbolAddress((void**)&WKVT, gb_wkv);
    cudaGetSymbolAddress((void**)&WOUTT,gb_wout);
    cudaGetSymbolAddress((void**)&G1T,  gb_g1);
    cudaGetSymbolAddress((void**)&G2T,  gb_g2);
    cudaGetSymbolAddress((void**)&FF1T, gb_ff1);
    cudaGetSymbolAddress((void**)&FF2T, gb_ff2);

    const size_t SZ = (size_t)DD * DD;

    // weight prep
    btpose_kernel<<<dim3(16, 16, 12), dim3(32, 8)>>>(g1W, g2W, G1T, G2T);
    launch_tpose(W_q,   WQT,   DD, 64);
    launch_tpose(W_kv,  WKVT,  DD, 128);
    launch_tpose(W_out, WOUTT, 64, DD);
    launch_tpose(ff_W1, FF1T, DD, DFF);
    launch_tpose(ff_W2, FF2T, DFF, DD);

    // activation converts
    cvt_kernel<<<(NROW * DD / 4 + 255) / 256, 256>>>(x, XB, NROW * DD / 4);
    cvt_kernel<<<(MM * BB * DD / 4 + 255) / 256, 256>>>(memory, MEMB, MM * BB * DD / 4);

    // pos emb
    prep_p_kernel<<<JJ, 64>>>(W_p, P);

    // LN1 -> LNB (bf16)
    ln_kernel<<<NROW / 8, 256>>>(x, LNB, ln1_g, ln1_b, NROW);

    // q = LN1 @ W_q (f32 out)
    launch_tc(LNB, WQT, DD, 0, 0, 0, NROW, 64, 64, Q, 0, 0, 0, 0.f, 0, 0, 0);

    // kv = [memory; LN1] @ W_kv (f32 out)
    launch_tc(MEMB, WKVT, DD, 0, 0, 0, MM * BB, 128, 128, KV, 0, 0, 0, 0.f, 0, 0, 0);
    launch_tc(LNB, WKVT, DD, 0, 0, 0, NROW, 128, 128, KV + (size_t)MM * BB * 128, 0, 0, 0, 0.f, 0, 0, 0);

    // attention -> AVB (bf16)
    attn_kernel<<<dim3(BB, HH), 128>>>(Q, KV, P, u, v, AVB);

    // y = av @ W_out -> YB (bf16)
    launch_tc(AVB, WOUTT, 64, 0, 0, 0, NROW, DD, 256, 0, YB, 0, 0, 0.f, 0, 0, 2);

    // gate 1: merged r/z phase, then combine phase
    launch_tc(YB, G1T + 0 * SZ, DD, XB, G1T + 1 * SZ, DD, NROW, DD, 256,
              0, RXB, g1b + 0 * DD, g1b + 1 * DD, 0.f, 0, x, 4,
              G1T + 2 * SZ, G1T + 3 * SZ, g1b + 2 * DD, g1b + 3 * DD, ZB);
    launch_tc(YB, G1T + 4 * SZ, DD, RXB, G1T + 5 * SZ, DD, NROW, DD, 256,
              B4, SRCB, g1b + 4 * DD, g1b + 5 * DD, 0.f, ZB, x, 5);

    // ff = relu(LN2(src)@W1+b1)@W2+b2 -> XB
    ln_kernel<<<NROW / 8, 256>>>(B4, LNB, ln2_g, ln2_b, NROW);
    launch_tc(LNB, FF1T, DD, 0, 0, 0, NROW, DFF, 64, 0, FFHB, ff_b1, 0, 0.f, 0, 0, 3);
    launch_tc(FFHB, FF2T, DFF, 0, 0, 0, NROW, DD, 256, 0, XB, ff_b2, 0, 0.f, 0, 0, 2);

    // gate 2: merged r/z phase, then combine -> B1 (f32)
    launch_tc(XB, G2T + 0 * SZ, DD, SRCB, G2T + 1 * SZ, DD, NROW, DD, 256,
              0, RXB, g2b + 0 * DD, g2b + 1 * DD, 0.f, 0, B4, 4,
              G2T + 2 * SZ, G2T + 3 * SZ, g2b + 2 * DD, g2b + 3 * DD, ZB);
    launch_tc(XB, G2T + 4 * SZ, DD, RXB, G2T + 5 * SZ, DD, NROW, DD, 256,
              B1, 0, g2b + 4 * DD, g2b + 5 * DD, 0.f, ZB, B4, 5);

    // mean pool
    meanpool_kernel<<<(BB * DD / 4 + 255) / 256, 256>>>((const float4*)B1, (float4*)TS);

    // critic head (exact fp32)
    launch_sgemm(TS, d1W, H1, BB, 1024, DD, d1b, 0.f, 2);
    launch_sgemm(H1, d2W, H2, BB, 512, 1024, nullptr, 0.f, 0);
    launch_sgemm(action, d2W + (size_t)1024 * 512, H2, BB, 512, ACT, d2b, 0.f, 3);
    launch_sgemm(H2, d3W, H3, BB, 300, DD, d3b, 0.f, 2);
    final_kernel<<<BB / 4, 128>>>(H3, d4W, d4b, (float*)d_out);
}

// round 8
// speedup vs baseline: 1.3503x; 1.3503x over previous
#include <cuda_runtime.h>
#include <cuda_bf16.h>
#include <math.h>
#include <stdint.h>

#define TT   128
#define BB   512
#define DD   512
#define MM   6
#define JJ   (TT + MM)
#define HH   2
#define DFF  64
#define ACT  64
#define NROW (TT * BB)
#define JROW (JJ * BB)
#define BG   0.1f

typedef __nv_bfloat16 bf16;

// ---------- static scratch ----------
__device__ __align__(256) float g_B1[NROW * DD];
__device__ __align__(256) float g_B4[NROW * DD];
__device__ __align__(256) float g_kv [JROW * 128];
__device__ __align__(256) float g_q  [NROW * 64];
__device__ __align__(256) float g_p  [JJ * 64];
__device__ __align__(256) float g_ts [BB * DD];
__device__ __align__(256) float g_h1 [BB * 1024];
__device__ __align__(256) float g_h2 [BB * 512];
__device__ __align__(256) float g_h3 [BB * 300];
__device__ __align__(256) bf16 gb_x  [NROW * DD];
__device__ __align__(256) bf16 gb_ln [NROW * DD];
__device__ __align__(256) bf16 gb_y  [NROW * DD];
__device__ __align__(256) bf16 gb_rx [NROW * DD];
__device__ __align__(256) bf16 gb_z  [NROW * DD];
__device__ __align__(256) bf16 gb_src[NROW * DD];
__device__ __align__(256) bf16 gb_ffh[NROW * DFF];
__device__ __align__(256) bf16 gb_av [NROW * 64];
__device__ __align__(256) bf16 gb_mem[MM * BB * DD];
__device__ __align__(256) bf16 gb_wq  [64 * DD];
__device__ __align__(256) bf16 gb_wkv [128 * DD];
__device__ __align__(256) bf16 gb_wout[DD * 64];
__device__ __align__(256) bf16 gb_g1  [6 * DD * DD];
__device__ __align__(256) bf16 gb_g2  [6 * DD * DD];
__device__ __align__(256) bf16 gb_ff1 [DFF * DD];
__device__ __align__(256) bf16 gb_ff2 [DD * DFF];

// ---------- helpers ----------
__device__ __forceinline__ uint32_t s2u(const void* p) {
    return (uint32_t)__cvta_generic_to_shared(p);
}
__device__ __forceinline__ void cp16(uint32_t s, const void* g) {
    asm volatile("cp.async.cg.shared.global [%0], [%1], 16;" :: "r"(s), "l"(g));
}
__device__ __forceinline__ void cp_commit() { asm volatile("cp.async.commit_group;" ::: "memory"); }
__device__ __forceinline__ void cp_wait0()  { asm volatile("cp.async.wait_group 0;" ::: "memory"); }
__device__ __forceinline__ void cp_wait1()  { asm volatile("cp.async.wait_group 1;" ::: "memory"); }
__device__ __forceinline__ void ldsm4(uint32_t* r, uint32_t addr) {
    asm volatile("ldmatrix.sync.aligned.m8n8.x4.shared.b16 {%0,%1,%2,%3}, [%4];"
                 : "=r"(r[0]), "=r"(r[1]), "=r"(r[2]), "=r"(r[3]) : "r"(addr));
}
__device__ __forceinline__ void mma_bf16(float* c, const uint32_t* a, const uint32_t* b) {
    asm volatile(
        "mma.sync.aligned.m16n8k16.row.col.f32.bf16.bf16.f32 "
        "{%0,%1,%2,%3}, {%4,%5,%6,%7}, {%8,%9}, {%0,%1,%2,%3};"
        : "+f"(c[0]), "+f"(c[1]), "+f"(c[2]), "+f"(c[3])
        : "r"(a[0]), "r"(a[1]), "r"(a[2]), "r"(a[3]), "r"(b[0]), "r"(b[1]));
}

// ---------- bf16 dual-source tensor GEMM (ldmatrix + 3-stage cp.async) ----------
// C[M,N] = A0[M,K0]@W0[N,K0]^T + A1[M,K1]@W1[N,K1]^T (+bias1+bias2+cadd)
// modes: 0 f32 | 2 bf16 | 3 bf16 relu | 4 bf16 = sigmoid(v)*aux
//        5 f32(+opt bf16) = (1-sig(zpre))*aux + sig(zpre)*tanh(v)
// If W0z != null: grid.x doubled; upper-half CTAs run the z-GEMM
// (same A pair, weights W0z/W1z, biases b1z/b2z, cadd=-BG, mode2 -> Cz).

template<int NT>
__global__ __launch_bounds__(256, 2)
void bgemm(const bf16* __restrict__ A0, const bf16* W0, int K0,
           const bf16* __restrict__ A1, const bf16* W1, int K1,
           int N,
           float* __restrict__ Cf, bf16* Cb,
           const float* bias1, const float* bias2,
           float cadd, const bf16* __restrict__ zpre, const float* __restrict__ aux,
           int mode,
           const bf16* W0z, const bf16* W1z,
           const float* b1z, const float* b2z, bf16* Cz)
{
    extern __shared__ char dsm[];
    constexpr int NTI = NT / 32;
    constexpr int STG = (128 + NT) * 144;

    const int tid  = threadIdx.x;
    const int warp = tid >> 5, lane = tid & 31;
    const int grp  = lane >> 2, thr = lane & 3;
    const int wm   = warp & 1,  wn  = warp >> 1;
    const int m_base = wm * 64;
    const int n_base = wn * (NT / 4);
    const int row0 = blockIdx.y * 128;
    int col0 = blockIdx.x * NT;
    const uint32_t sb = s2u(dsm);

    if (W0z && col0 >= N) {
        col0 -= N;
        W0 = W0z; W1 = W1z; bias1 = b1z; bias2 = b2z;
        cadd = -BG; mode = 2; Cb = Cz;
    }

    float acc[4][NTI][4];
#pragma unroll
    for (int i = 0; i < 4; i++)
#pragma unroll
        for (int j = 0; j < NTI; j++)
#pragma unroll
            for (int r = 0; r < 4; r++) acc[i][j][r] = 0.f;

    const int NC0 = K0 >> 6;
    const int NC  = NC0 + (K1 >> 6);

    auto load_stage = [&](int c, int buf) {
        const bf16 *a, *w; int k, kb;
        if (c < NC0) { a = A0; w = W0; k = K0; kb = c << 6; }
        else         { a = A1; w = W1; k = K1; kb = (c - NC0) << 6; }
        uint32_t ab = sb + (uint32_t)buf * STG;
#pragma unroll
        for (int i = 0; i < 4; i++) {
            int u = tid + i * 256;
            int r = u >> 3, cc = u & 7;
            cp16(ab + (uint32_t)(r * 144 + cc * 16),
                 a + (size_t)(row0 + r) * k + kb + cc * 8);
        }
        uint32_t bb = ab + 128u * 144u;
#pragma unroll
        for (int i = 0; i < NT / 32; i++) {
            int u = tid + i * 256;
            int r = u >> 3, cc = u & 7;
            cp16(bb + (uint32_t)(r * 144 + cc * 16),
                 w + (size_t)(col0 + r) * k + kb + cc * 8);
        }
        cp_commit();
    };

    load_stage(0, 0);
    if (NC > 1) load_stage(1, 1);

    for (int c = 0; c < NC; c++) {
        if (c == NC - 1) cp_wait0(); else cp_wait1();
        __syncthreads();
        if (c + 2 < NC) load_stage(c + 2, (c + 2) % 3);

        uint32_t ab = sb + (uint32_t)(c % 3) * STG;
        uint32_t bb = ab + 128u * 144u;

        const uint32_t a_lrow = (uint32_t)(lane & 15);
        const uint32_t a_koff = (uint32_t)((lane >> 4) << 3);
        const uint32_t b_cofs = (uint32_t)(((lane >> 4) << 3) + (lane & 7));
        const uint32_t b_koff = (uint32_t)(((lane >> 3) & 1) << 3);

#pragma unroll
        for (int ks = 0; ks < 4; ks++) {
            const int kc = ks * 16;
            uint32_t af[4][4], bfr[NTI][2];
#pragma unroll
            for (int mt = 0; mt < 4; mt++) {
                uint32_t addr = ab + (uint32_t)(m_base + mt * 16 + a_lrow) * 144u
                                   + (uint32_t)(kc + a_koff) * 2u;
                ldsm4(af[mt], addr);
            }
#pragma unroll
            for (int p = 0; p < NTI / 2; p++) {
                uint32_t col = (uint32_t)(n_base + p * 16) + b_cofs;
                uint32_t addr = bb + col * 144u + (uint32_t)(kc + b_koff) * 2u;
                uint32_t r[4];
                ldsm4(r, addr);
                bfr[2 * p][0]     = r[0]; bfr[2 * p][1]     = r[1];
                bfr[2 * p + 1][0] = r[2]; bfr[2 * p + 1][1] = r[3];
            }
#pragma unroll
            for (int mt = 0; mt < 4; mt++)
#pragma unroll
                for (int nt = 0; nt < NTI; nt++)
                    mma_bf16(acc[mt][nt], af[mt], bfr[nt]);
        }
    }

    // epilogue
#pragma unroll
    for (int mt = 0; mt < 4; mt++) {
#pragma unroll
        for (int nt = 0; nt < NTI; nt++) {
            int cbase = col0 + n_base + nt * 8 + thr * 2;
            float b0 = cadd, b1 = cadd;
            if (bias1) { b0 += bias1[cbase]; b1 += bias1[cbase + 1]; }
            if (bias2) { b0 += bias2[cbase]; b1 += bias2[cbase + 1]; }
#pragma unroll
            for (int half = 0; half < 2; half++) {
                int r = row0 + m_base + mt * 16 + grp + half * 8;
                size_t idx0 = (size_t)r * N + cbase;
#pragma unroll
                for (int e = 0; e < 2; e++) {
                    float v = acc[mt][nt][half * 2 + e] + (e ? b1 : b0);
                    size_t idx = idx0 + e;
                    if (mode == 0) {
                        Cf[idx] = v;
                    } else if (mode == 2) {
                        Cb[idx] = __float2bfloat16(v);
                    } else if (mode == 3) {
                        Cb[idx] = __float2bfloat16(fmaxf(v, 0.f));
                    } else if (mode == 4) {
                        float s = 1.f / (1.f + __expf(-v));
                        Cb[idx] = __float2bfloat16(s * aux[idx]);
                    } else {
                        float z = 1.f / (1.f + __expf(-__bfloat162float(zpre[idx])));
                        float o = (1.f - z) * aux[idx] + z * tanhf(v);
                        Cf[idx] = o;
                        if (Cb) Cb[idx] = __float2bfloat16(o);
                    }
                }
            }
        }
    }
}

// ---------- exact fp32 GEMM, 64x64 tiles (critic head) ----------
__global__ void sgemm64_kernel(const float* __restrict__ A, const float* __restrict__ W,
                               float* __restrict__ C, int M, int N, int K,
                               const float* __restrict__ bias, float cadd, int flags)
{
    __shared__ float As[8][64];
    __shared__ float Bs[8][65];
    int tid = threadIdx.x;
    int row0 = blockIdx.y * 64, col0 = blockIdx.x * 64;
    int tx = tid & 15, ty = tid >> 4;
    float acc[4][4];
#pragma unroll
    for (int i = 0; i < 4; i++)
#pragma unroll
        for (int j = 0; j < 4; j++) acc[i][j] = 0.f;

    int ar = tid >> 2, ac2 = (tid & 3) * 2;
    int br = tid >> 5, bc = tid & 31;

    for (int k0 = 0; k0 < K; k0 += 8) {
        float2 a2 = *reinterpret_cast<const float2*>(A + (size_t)(row0 + ar) * K + k0 + ac2);
        As[ac2][ar] = a2.x;
        As[ac2 + 1][ar] = a2.y;
        float w0 = (col0 + bc < N)      ? W[(size_t)(k0 + br) * N + col0 + bc]      : 0.f;
        float w1 = (col0 + bc + 32 < N) ? W[(size_t)(k0 + br) * N + col0 + bc + 32] : 0.f;
        Bs[br][bc] = w0;
        Bs[br][bc + 32] = w1;
        __syncthreads();
#pragma unroll
        for (int kk = 0; kk < 8; kk++) {
            float av[4], bv[4];
#pragma unroll
            for (int i = 0; i < 4; i++) av[i] = As[kk][ty * 4 + i];
#pragma unroll
            for (int j = 0; j < 4; j++) bv[j] = Bs[kk][tx * 4 + j];
#pragma unroll
            for (int i = 0; i < 4; i++)
#pragma unroll
                for (int j = 0; j < 4; j++) acc[i][j] += av[i] * bv[j];
        }
        __syncthreads();
    }
#pragma unroll
    for (int i = 0; i < 4; i++) {
        int r = row0 + ty * 4 + i;
        if (r >= M) continue;
#pragma unroll
        for (int j = 0; j < 4; j++) {
            int c = col0 + tx * 4 + j;
            if (c >= N) continue;
            float val = acc[i][j] + cadd;
            if (bias) val += bias[c];
            size_t idx = (size_t)r * N + c;
            if (flags & 1) val += C[idx];
            if (flags & 2) val = fmaxf(val, 0.f);
            C[idx] = val;
        }
    }
}

// ---------- LayerNorm (bf16 out) ----------
__global__ void ln_kernel(const float* __restrict__ x, bf16* __restrict__ out,
                          const float* __restrict__ g, const float* __restrict__ b, int rows)
{
    int warp = blockIdx.x * (blockDim.x >> 5) + (threadIdx.x >> 5);
    if (warp >= rows) return;
    int lane = threadIdx.x & 31;
    const float* xr = x + (size_t)warp * DD;
    float v[16], s1 = 0.f, s2 = 0.f;
#pragma unroll
    for (int i = 0; i < 16; i++) {
        float t = xr[i * 32 + lane];
        v[i] = t; s1 += t; s2 += t * t;
    }
#pragma unroll
    for (int o = 16; o; o >>= 1) {
        s1 += __shfl_xor_sync(0xffffffffu, s1, o);
        s2 += __shfl_xor_sync(0xffffffffu, s2, o);
    }
    float mu = s1 * (1.f / DD);
    float inv = rsqrtf(s2 * (1.f / DD) - mu * mu + 1e-5f);
    bf16* orow = out + (size_t)warp * DD;
#pragma unroll
    for (int i = 0; i < 16; i++) {
        int d = i * 32 + lane;
        orow[d] = __float2bfloat16((v[i] - mu) * inv * g[d] + b[d]);
    }
}

// ---------- pos-emb @ W_p ----------
__global__ void prep_p_kernel(const float* __restrict__ Wp, float* __restrict__ p)
{
    int jj = blockIdx.x;
    __shared__ float pe[DD];
    float pos = (float)(JJ - 1 - jj);
    for (int d = threadIdx.x; d < DD; d += 64) {
        int i = (d < 256) ? d : d - 256;
        float f = __expf(-(float)(2 * i) * (1.f / 512.f) * 9.210340371976184f);
        float a = pos * f;
        pe[d] = (d < 256) ? sinf(a) : cosf(a);
    }
    __syncthreads();
    int c = threadIdx.x;
    float acc = 0.f;
    for (int d = 0; d < DD; d++) acc += pe[d] * Wp[d * 64 + c];
    p[jj * 64 + c] = acc;
}

// ---------- attention (bf16 av out) ----------
__global__ void attn_kernel(const float* __restrict__ q, const float* __restrict__ kv,
                            const float* __restrict__ p, const float* __restrict__ uu,
                            const float* __restrict__ vvec, bf16* __restrict__ av)
{
    int b = blockIdx.x, h = blockIdx.y;
    __shared__ float Ks[JJ][33];
    __shared__ float Vs[JJ][33];
    __shared__ float att[4][JJ];
    __shared__ float qsu[4][32];
    __shared__ float qsv[4][32];
    int tid = threadIdx.x;
    for (int idx = tid; idx < JJ * 32; idx += 128) {
        int j = idx >> 5, d = idx & 31;
        const float* row = kv + ((size_t)j * BB + b) * 128 + h * 32 + d;
        Ks[j][d] = row[0];
        Vs[j][d] = row[64];
    }
    __syncthreads();
    int warp = tid >> 5, lane = tid & 31;
    float ul = uu[h * 32 + lane], vl = vvec[h * 32 + lane];
    for (int i = warp; i < TT; i += 4) {
        float qv = q[((size_t)i * BB + b) * 64 + h * 32 + lane];
        qsu[warp][lane] = qv + ul;
        qsv[warp][lane] = qv + vl;
        __syncwarp();
        int jmax = i + MM;
        float sv[5], smax = -1e30f;
        int cnt = 0;
        for (int j = lane; j <= jmax; j += 32) {
            const float* prow = p + (size_t)(j + TT - 1 - i) * 64 + h * 32;
            float s = 0.f;
#pragma unroll
            for (int d = 0; d < 32; d++)
                s += qsu[warp][d] * Ks[j][d] + qsv[warp][d] * prow[d];
            s *= 0.1767766952966369f;
            sv[cnt++] = s;
            smax = fmaxf(smax, s);
        }
#pragma unroll
        for (int o = 16; o; o >>= 1) smax = fmaxf(smax, __shfl_xor_sync(0xffffffffu, smax, o));
        float sum = 0.f; cnt = 0;
        for (int j = lane; j <= jmax; j += 32) {
            float e = __expf(sv[cnt++] - smax);
            att[warp][j] = e;
            sum += e;
        }
#pragma unroll
        for (int o = 16; o; o >>= 1) sum += __shfl_xor_sync(0xffffffffu, sum, o);
        float inv = 1.f / sum;
        __syncwarp();
        float acc = 0.f;
        for (int j = 0; j <= jmax; j++) acc += att[warp][j] * Vs[j][lane];
        av[((size_t)i * BB + b) * 64 + h * 32 + lane] = __float2bfloat16(acc * inv);
        __syncwarp();
    }
}

// ---------- transpose+convert W[K,N] f32 -> [N,K] bf16 ----------
__global__ void tpose_kernel(const float* __restrict__ in, bf16* __restrict__ out, int K, int N)
{
    __shared__ float t[32][33];
    int k0 = blockIdx.y * 32, n0 = blockIdx.x * 32;
    int x = threadIdx.x, y = threadIdx.y;
    for (int i = y; i < 32; i += 8)
        t[i][x] = in[(size_t)(k0 + i) * N + n0 + x];
    __syncthreads();
    for (int i = y; i < 32; i += 8)
        out[(size_t)(n0 + i) * K + k0 + x] = __float2bfloat16(t[x][i]);
}

// ---------- batched transpose for the 12 gate matrices (512x512) ----------
__global__ void btpose_kernel(const float* __restrict__ g1, const float* __restrict__ g2,
                              bf16* __restrict__ o1, bf16* __restrict__ o2)
{
    __shared__ float t[32][33];
    int z = blockIdx.z;
    const float* in = (z < 6) ? (g1 + (size_t)z * DD * DD) : (g2 + (size_t)(z - 6) * DD * DD);
    bf16* out = (z < 6) ? (o1 + (size_t)z * DD * DD) : (o2 + (size_t)(z - 6) * DD * DD);
    int k0 = blockIdx.y * 32, n0 = blockIdx.x * 32;
    int x = threadIdx.x, y = threadIdx.y;
    for (int i = y; i < 32; i += 8)
        t[i][x] = in[(size_t)(k0 + i) * DD + n0 + x];
    __syncthreads();
    for (int i = y; i < 32; i += 8)
        out[(size_t)(n0 + i) * DD + k0 + x] = __float2bfloat16(t[x][i]);
}

// ---------- f32 -> bf16 ----------
__global__ void cvt_kernel(const float* __restrict__ in, bf16* __restrict__ out, int n4)
{
    int i = blockIdx.x * blockDim.x + threadIdx.x;
    if (i >= n4) return;
    float4 v = reinterpret_cast<const float4*>(in)[i];
    __nv_bfloat162* o = reinterpret_cast<__nv_bfloat162*>(out + (size_t)i * 4);
    o[0] = __floats2bfloat162_rn(v.x, v.y);
    o[1] = __floats2bfloat162_rn(v.z, v.w);
}

// ---------- mean pool (vectorized) ----------
__global__ void meanpool_kernel(const float4* __restrict__ in, float4* __restrict__ ts)
{
    int idx = blockIdx.x * blockDim.x + threadIdx.x;
    const int n4 = BB * DD / 4;
    if (idx >= n4) return;
    float4 s = make_float4(0.f, 0.f, 0.f, 0.f);
    for (int t = 0; t < TT; t++) {
        float4 v = in[(size_t)t * n4 + idx];
        s.x += v.x; s.y += v.y; s.z += v.z; s.w += v.w;
    }
    const float inv = 1.f / TT;
    s.x *= inv; s.y *= inv; s.z *= inv; s.w *= inv;
    ts[idx] = s;
}

// ---------- final head ----------
__global__ void final_kernel(const float* __restrict__ h3, const float* __restrict__ w,
                             const float* __restrict__ bb, float* __restrict__ out)
{
    int row = blockIdx.x * 4 + (threadIdx.x >> 5);
    int lane = threadIdx.x & 31;
    if (row >= BB) return;
    float s = 0.f;
    for (int k = lane; k < 300; k += 32) s += h3[(size_t)row * 300 + k] * w[k];
#pragma unroll
    for (int o = 16; o; o >>= 1) s += __shfl_xor_sync(0xffffffffu, s, o);
    if (lane == 0) out[row] = fmaxf(s + bb[0], 0.f);
}

// ---------- host ----------
static inline void launch_tc(const bf16* A0, const bf16* W0, int K0,
                             const bf16* A1, const bf16* W1, int K1,
                             int M, int N, int NT,
                             float* Cf, bf16* Cb,
                             const float* b1, const float* b2, float cadd,
                             const bf16* zpre, const float* aux, int mode,
                             const bf16* W0z = 0, const bf16* W1z = 0,
                             const float* b1z = 0, const float* b2z = 0, bf16* Cz = 0)
{
    int gx = (W0z ? 2 * N : N) / NT;
    dim3 grid(gx, M / 128);
    if (NT == 128) {
        size_t dsz = 3 * (size_t)(128 + 128) * 144;
        bgemm<128><<<grid, 256, dsz>>>(A0, W0, K0, A1, W1, K1, N, Cf, Cb, b1, b2, cadd,
                                       zpre, aux, mode, W0z, W1z, b1z, b2z, Cz);
    } else {
        size_t dsz = 3 * (size_t)(128 + 64) * 144;
        bgemm<64><<<grid, 256, dsz>>>(A0, W0, K0, A1, W1, K1, N, Cf, Cb, b1, b2, cadd,
                                      zpre, aux, mode, W0z, W1z, b1z, b2z, Cz);
    }
}
static inline void launch_sgemm(const float* A, const float* W, float* C,
                                int M, int N, int K, const float* bias, float cadd, int flags)
{
    dim3 grid((N + 63) / 64, (M + 63) / 64);
    sgemm64_kernel<<<grid, 256>>>(A, W, C, M, N, K, bias, cadd, flags);
}
static inline void launch_tpose(const float* in, bf16* out, int K, int N)
{
    tpose_kernel<<<dim3(N / 32, K / 32), dim3(32, 8)>>>(in, out, K, N);
}

extern "C" void kernel_launch(void* const* d_in, const int* in_sizes, int n_in,
                              void* d_out, int out_size)
{
    const float* x      = (const float*)d_in[0];
    const float* action = (const float*)d_in[1];
    const float* memory = (const float*)d_in[2];
    const float* W_q    = (const float*)d_in[3];
    const float* W_kv   = (const float*)d_in[4];
    const float* W_p    = (const float*)d_in[5];
    const float* W_out  = (const float*)d_in[6];
    const float* u      = (const float*)d_in[7];
    const float* v      = (const float*)d_in[8];
    const float* ln1_g  = (const float*)d_in[9];
    const float* ln1_b  = (const float*)d_in[10];
    const float* ln2_g  = (const float*)d_in[11];
    const float* ln2_b  = (const float*)d_in[12];
    const float* ff_W1  = (const float*)d_in[13];
    const float* ff_b1  = (const float*)d_in[14];
    const float* ff_W2  = (const float*)d_in[15];
    const float* ff_b2  = (const float*)d_in[16];
    const float* g1W    = (const float*)d_in[17];
    const float* g1b    = (const float*)d_in[18];
    const float* g2W    = (const float*)d_in[19];
    const float* g2b    = (const float*)d_in[20];
    const float* d1W    = (const float*)d_in[21];
    const float* d1b    = (const float*)d_in[22];
    const float* d2W    = (const float*)d_in[23];
    const float* d2b    = (const float*)d_in[24];
    const float* d3W    = (const float*)d_in[25];
    const float* d3b    = (const float*)d_in[26];
    const float* d4W    = (const float*)d_in[27];
    const float* d4b    = (const float*)d_in[28];

    cudaFuncSetAttribute(bgemm<128>, cudaFuncAttributeMaxDynamicSharedMemorySize, 111000);
    cudaFuncSetAttribute(bgemm<64>,  cudaFuncAttributeMaxDynamicSharedMemorySize, 84000);

    float *B1, *B4, *KV, *Q, *P, *TS, *H1, *H2, *H3;
    bf16 *XB, *LNB, *YB, *RXB, *ZB, *SRCB, *FFHB, *AVB, *MEMB;
    bf16 *WQT, *WKVT, *WOUTT, *G1T, *G2T, *FF1T, *FF2T;
    cudaGetSymbolAddress((void**)&B1,   g_B1);
    cudaGetSymbolAddress((void**)&B4,   g_B4);
    cudaGetSymbolAddress((void**)&KV,   g_kv);
    cudaGetSymbolAddress((void**)&Q,    g_q);
    cudaGetSymbolAddress((void**)&P,    g_p);
    cudaGetSymbolAddress((void**)&TS,   g_ts);
    cudaGetSymbolAddress((void**)&H1,   g_h1);
    cudaGetSymbolAddress((void**)&H2,   g_h2);
    cudaGetSymbolAddress((void**)&H3,   g_h3);
    cudaGetSymbolAddress((void**)&XB,   gb_x);
    cudaGetSymbolAddress((void**)&LNB,  gb_ln);
    cudaGetSymbolAddress((void**)&YB,   gb_y);
    cudaGetSymbolAddress((void**)&RXB,  gb_rx);
    cudaGetSymbolAddress((void**)&ZB,   gb_z);
    cudaGetSymbolAddress((void**)&SRCB, gb_src);
    cudaGetSymbolAddress((void**)&FFHB, gb_ffh);
    cudaGetSymbolAddress((void**)&AVB,  gb_av);
    cudaGetSymbolAddress((void**)&MEMB, gb_mem);
    cudaGetSymbolAddress((void**)&WQT,  gb_wq);
    cudaGetSymbolAddress((void**)&WKVT, gb_wkv);
    cudaGetSymbolAddress((void**)&WOUTT,gb_wout);
    cudaGetSymbolAddress((void**)&G1T,  gb_g1);
    cudaGetSymbolAddress((void**)&G2T,  gb_g2);
    cudaGetSymbolAddress((void**)&FF1T, gb_ff1);
    cudaGetSymbolAddress((void**)&FF2T, gb_ff2);

    const size_t SZ = (size_t)DD * DD;

    // weight prep
    btpose_kernel<<<dim3(16, 16, 12), dim3(32, 8)>>>(g1W, g2W, G1T, G2T);
    launch_tpose(W_q,   WQT,   DD, 64);
    launch_tpose(W_kv,  WKVT,  DD, 128);
    launch_tpose(W_out, WOUTT, 64, DD);
    launch_tpose(ff_W1, FF1T, DD, DFF);
    launch_tpose(ff_W2, FF2T, DFF, DD);

    // activation converts
    cvt_kernel<<<(NROW * DD / 4 + 255) / 256, 256>>>(x, XB, NROW * DD / 4);
    cvt_kernel<<<(MM * BB * DD / 4 + 255) / 256, 256>>>(memory, MEMB, MM * BB * DD / 4);

    // pos emb
    prep_p_kernel<<<JJ, 64>>>(W_p, P);

    // LN1 -> LNB (bf16)
    ln_kernel<<<NROW / 8, 256>>>(x, LNB, ln1_g, ln1_b, NROW);

    // q = LN1 @ W_q (f32 out)
    launch_tc(LNB, WQT, DD, 0, 0, 0, NROW, 64, 64, Q, 0, 0, 0, 0.f, 0, 0, 0);

    // kv = [memory; LN1] @ W_kv (f32 out)
    launch_tc(MEMB, WKVT, DD, 0, 0, 0, MM * BB, 128, 128, KV, 0, 0, 0, 0.f, 0, 0, 0);
    launch_tc(LNB, WKVT, DD, 0, 0, 0, NROW, 128, 128, KV + (size_t)MM * BB * 128, 0, 0, 0, 0.f, 0, 0, 0);

    // attention -> AVB (bf16)
    attn_kernel<<<dim3(BB, HH), 128>>>(Q, KV, P, u, v, AVB);

    // y = av @ W_out -> YB (bf16)
    launch_tc(AVB, WOUTT, 64, 0, 0, 0, NROW, DD, 128, 0, YB, 0, 0, 0.f, 0, 0, 2);

    // gate 1: merged r/z phase (grid.x doubled), then combine
    launch_tc(YB, G1T + 0 * SZ, DD, XB, G1T + 1 * SZ, DD, NROW, DD, 128,
              0, RXB, g1b + 0 * DD, g1b + 1 * DD, 0.f, 0, x, 4,
              G1T + 2 * SZ, G1T + 3 * SZ, g1b + 2 * DD, g1b + 3 * DD, ZB);
    launch_tc(YB, G1T + 4 * SZ, DD, RXB, G1T + 5 * SZ, DD, NROW, DD, 128,
              B4, SRCB, g1b + 4 * DD, g1b + 5 * DD, 0.f, ZB, x, 5);

    // ff = relu(LN2(src)@W1+b1)@W2+b2 -> XB
    ln_kernel<<<NROW / 8, 256>>>(B4, LNB, ln2_g, ln2_b, NROW);
    launch_tc(LNB, FF1T, DD, 0, 0, 0, NROW, DFF, 64, 0, FFHB, ff_b1, 0, 0.f, 0, 0, 3);
    launch_tc(FFHB, FF2T, DFF, 0, 0, 0, NROW, DD, 128, 0, XB, ff_b2, 0, 0.f, 0, 0, 2);

    // gate 2: merged r/z phase, then combine -> B1 (f32)
    launch_tc(XB, G2T + 0 * SZ, DD, SRCB, G2T + 1 * SZ, DD, NROW, DD, 128,
              0, RXB, g2b + 0 * DD, g2b + 1 * DD, 0.f, 0, B4, 4,
              G2T + 2 * SZ, G2T + 3 * SZ, g2b + 2 * DD, g2b + 3 * DD, ZB);
    launch_tc(XB, G2T + 4 * SZ, DD, RXB, G2T + 5 * SZ, DD, NROW, DD, 128,
              B1, 0, g2b + 4 * DD, g2b + 5 * DD, 0.f, ZB, B4, 5);

    // mean pool
    meanpool_kernel<<<(BB * DD / 4 + 255) / 256, 256>>>((const float4*)B1, (float4*)TS);

    // critic head (exact fp32)
    launch_sgemm(TS, d1W, H1, BB, 1024, DD, d1b, 0.f, 2);
    launch_sgemm(H1, d2W, H2, BB, 512, 1024, nullptr, 0.f, 0);
    launch_sgemm(action, d2W + (size_t)1024 * 512, H2, BB, 512, ACT, d2b, 0.f, 3);
    launch_sgemm(H2, d3W, H3, BB, 300, DD, d3b, 0.f, 2);
    final_kernel<<<BB / 4, 128>>>(H3, d4W, d4b, (float*)d_out);
}

// round 9
// speedup vs baseline: 1.4425x; 1.0683x over previous
#include <cuda_runtime.h>
#include <cuda_bf16.h>
#include <math.h>
#include <stdint.h>

#define TT   128
#define BB   512
#define DD   512
#define MM   6
#define JJ   (TT + MM)
#define HH   2
#define DFF  64
#define ACT  64
#define NROW (TT * BB)
#define BG   0.1f

typedef __nv_bfloat16 bf16;

// ---------- static scratch ----------
__device__ __align__(256) float g_B1[NROW * DD];
__device__ __align__(256) float g_B4[NROW * DD];
__device__ __align__(256) float g_qkv[NROW * 192];          // fused q|k|v for src rows
__device__ __align__(256) float g_kvm[MM * BB * 128];       // memory-rows kv
__device__ __align__(256) float g_p  [JJ * 64];
__device__ __align__(256) float g_ts [BB * DD];
__device__ __align__(256) float g_h1 [BB * 1024];
__device__ __align__(256) float g_h2 [BB * 512];
__device__ __align__(256) float g_h3 [BB * 300];
__device__ __align__(256) bf16 gb_x  [NROW * DD];
__device__ __align__(256) bf16 gb_ln [NROW * DD];
__device__ __align__(256) bf16 gb_y  [NROW * DD];
__device__ __align__(256) bf16 gb_rx [NROW * DD];
__device__ __align__(256) bf16 gb_z  [NROW * DD];
__device__ __align__(256) bf16 gb_src[NROW * DD];
__device__ __align__(256) bf16 gb_ffh[NROW * DFF];
__device__ __align__(256) bf16 gb_av [NROW * 64];
__device__ __align__(256) bf16 gb_mem[MM * BB * DD];
__device__ __align__(256) bf16 gb_wqkv[192 * DD];           // rows 0-63 Wq^T, 64-191 Wkv^T
__device__ __align__(256) bf16 gb_wout[DD * 64];
__device__ __align__(256) bf16 gb_g1  [6 * DD * DD];
__device__ __align__(256) bf16 gb_g2  [6 * DD * DD];
__device__ __align__(256) bf16 gb_ff1 [DFF * DD];
__device__ __align__(256) bf16 gb_ff2 [DD * DFF];

// ---------- helpers ----------
__device__ __forceinline__ uint32_t s2u(const void* p) {
    return (uint32_t)__cvta_generic_to_shared(p);
}
__device__ __forceinline__ void cp16(uint32_t s, const void* g) {
    asm volatile("cp.async.cg.shared.global [%0], [%1], 16;" :: "r"(s), "l"(g));
}
__device__ __forceinline__ void cp_commit() { asm volatile("cp.async.commit_group;" ::: "memory"); }
__device__ __forceinline__ void cp_wait0()  { asm volatile("cp.async.wait_group 0;" ::: "memory"); }
__device__ __forceinline__ void cp_wait1()  { asm volatile("cp.async.wait_group 1;" ::: "memory"); }
__device__ __forceinline__ void ldsm4(uint32_t* r, uint32_t addr) {
    asm volatile("ldmatrix.sync.aligned.m8n8.x4.shared.b16 {%0,%1,%2,%3}, [%4];"
                 : "=r"(r[0]), "=r"(r[1]), "=r"(r[2]), "=r"(r[3]) : "r"(addr));
}
__device__ __forceinline__ void mma_bf16(float* c, const uint32_t* a, const uint32_t* b) {
    asm volatile(
        "mma.sync.aligned.m16n8k16.row.col.f32.bf16.bf16.f32 "
        "{%0,%1,%2,%3}, {%4,%5,%6,%7}, {%8,%9}, {%0,%1,%2,%3};"
        : "+f"(c[0]), "+f"(c[1]), "+f"(c[2]), "+f"(c[3])
        : "r"(a[0]), "r"(a[1]), "r"(a[2]), "r"(a[3]), "r"(b[0]), "r"(b[1]));
}

// ---------- bf16 dual-source tensor GEMM (ldmatrix + 3-stage cp.async) ----------
// C[M,N] = A0[M,K0]@W0[N,K0]^T + A1[M,K1]@W1[N,K1]^T (+bias1+bias2+cadd)
// modes: 0 f32 | 2 bf16 | 3 bf16 relu | 4 bf16 = sigmoid(v)*aux
//        5 f32(+opt bf16) = (1-sig(zpre))*aux + sig(zpre)*tanh(v)
// Requirements: M%128==0, N%NT==0, K0,K1 % 64 == 0.

template<int NT>
__global__ __launch_bounds__(256, 2)
void bgemm(const bf16* __restrict__ A0, const bf16* __restrict__ W0, int K0,
           const bf16* __restrict__ A1, const bf16* __restrict__ W1, int K1,
           int N,
           float* __restrict__ Cf, bf16* __restrict__ Cb,
           const float* __restrict__ bias1, const float* __restrict__ bias2,
           float cadd, const bf16* __restrict__ zpre, const float* __restrict__ aux,
           int mode)
{
    extern __shared__ char dsm[];
    constexpr int NTI = NT / 32;
    constexpr int STG = (128 + NT) * 144;

    const int tid  = threadIdx.x;
    const int warp = tid >> 5, lane = tid & 31;
    const int grp  = lane >> 2, thr = lane & 3;
    const int wm   = warp & 1,  wn  = warp >> 1;
    const int m_base = wm * 64;
    const int n_base = wn * (NT / 4);
    const int row0 = blockIdx.y * 128;
    const int col0 = blockIdx.x * NT;
    const uint32_t sb = s2u(dsm);

    float acc[4][NTI][4];
#pragma unroll
    for (int i = 0; i < 4; i++)
#pragma unroll
        for (int j = 0; j < NTI; j++)
#pragma unroll
            for (int r = 0; r < 4; r++) acc[i][j][r] = 0.f;

    const int NC0 = K0 >> 6;
    const int NC  = NC0 + (K1 >> 6);

    auto load_stage = [&](int c, int buf) {
        const bf16 *a, *w; int k, kb;
        if (c < NC0) { a = A0; w = W0; k = K0; kb = c << 6; }
        else         { a = A1; w = W1; k = K1; kb = (c - NC0) << 6; }
        uint32_t ab = sb + (uint32_t)buf * STG;
#pragma unroll
        for (int i = 0; i < 4; i++) {
            int u = tid + i * 256;
            int r = u >> 3, cc = u & 7;
            cp16(ab + (uint32_t)(r * 144 + cc * 16),
                 a + (size_t)(row0 + r) * k + kb + cc * 8);
        }
        uint32_t bb = ab + 128u * 144u;
#pragma unroll
        for (int i = 0; i < NT / 32; i++) {
            int u = tid + i * 256;
            int r = u >> 3, cc = u & 7;
            cp16(bb + (uint32_t)(r * 144 + cc * 16),
                 w + (size_t)(col0 + r) * k + kb + cc * 8);
        }
        cp_commit();
    };

    load_stage(0, 0);
    if (NC > 1) load_stage(1, 1);

    for (int c = 0; c < NC; c++) {
        if (c == NC - 1) cp_wait0(); else cp_wait1();
        __syncthreads();
        if (c + 2 < NC) load_stage(c + 2, (c + 2) % 3);

        uint32_t ab = sb + (uint32_t)(c % 3) * STG;
        uint32_t bb = ab + 128u * 144u;

        const uint32_t a_lrow = (uint32_t)(lane & 15);
        const uint32_t a_koff = (uint32_t)((lane >> 4) << 3);
        const uint32_t b_cofs = (uint32_t)(((lane >> 4) << 3) + (lane & 7));
        const uint32_t b_koff = (uint32_t)(((lane >> 3) & 1) << 3);

#pragma unroll
        for (int ks = 0; ks < 4; ks++) {
            const int kc = ks * 16;
            uint32_t af[4][4], bfr[NTI][2];
#pragma unroll
            for (int mt = 0; mt < 4; mt++) {
                uint32_t addr = ab + (uint32_t)(m_base + mt * 16 + a_lrow) * 144u
                                   + (uint32_t)(kc + a_koff) * 2u;
                ldsm4(af[mt], addr);
            }
#pragma unroll
            for (int p = 0; p < NTI / 2; p++) {
                uint32_t col = (uint32_t)(n_base + p * 16) + b_cofs;
                uint32_t addr = bb + col * 144u + (uint32_t)(kc + b_koff) * 2u;
                uint32_t r[4];
                ldsm4(r, addr);
                bfr[2 * p][0]     = r[0]; bfr[2 * p][1]     = r[1];
                bfr[2 * p + 1][0] = r[2]; bfr[2 * p + 1][1] = r[3];
            }
#pragma unroll
            for (int mt = 0; mt < 4; mt++)
#pragma unroll
                for (int nt = 0; nt < NTI; nt++)
                    mma_bf16(acc[mt][nt], af[mt], bfr[nt]);
        }
    }

    // epilogue
#pragma unroll
    for (int mt = 0; mt < 4; mt++) {
#pragma unroll
        for (int nt = 0; nt < NTI; nt++) {
            int cbase = col0 + n_base + nt * 8 + thr * 2;
            float b0 = cadd, b1 = cadd;
            if (bias1) { b0 += bias1[cbase]; b1 += bias1[cbase + 1]; }
            if (bias2) { b0 += bias2[cbase]; b1 += bias2[cbase + 1]; }
#pragma unroll
            for (int half = 0; half < 2; half++) {
                int r = row0 + m_base + mt * 16 + grp + half * 8;
                size_t idx0 = (size_t)r * N + cbase;
#pragma unroll
                for (int e = 0; e < 2; e++) {
                    float v = acc[mt][nt][half * 2 + e] + (e ? b1 : b0);
                    size_t idx = idx0 + e;
                    if (mode == 0) {
                        Cf[idx] = v;
                    } else if (mode == 2) {
                        Cb[idx] = __float2bfloat16(v);
                    } else if (mode == 3) {
                        Cb[idx] = __float2bfloat16(fmaxf(v, 0.f));
                    } else if (mode == 4) {
                        float s = 1.f / (1.f + __expf(-v));
                        Cb[idx] = __float2bfloat16(s * aux[idx]);
                    } else {
                        float z = 1.f / (1.f + __expf(-__bfloat162float(zpre[idx])));
                        float o = (1.f - z) * aux[idx] + z * tanhf(v);
                        Cf[idx] = o;
                        if (Cb) Cb[idx] = __float2bfloat16(o);
                    }
                }
            }
        }
    }
}

// ---------- exact fp32 GEMM, 64x64 tiles (critic head) ----------
__global__ void sgemm64_kernel(const float* __restrict__ A, const float* __restrict__ W,
                               float* __restrict__ C, int M, int N, int K,
                               const float* __restrict__ bias, float cadd, int flags)
{
    __shared__ float As[8][64];
    __shared__ float Bs[8][65];
    int tid = threadIdx.x;
    int row0 = blockIdx.y * 64, col0 = blockIdx.x * 64;
    int tx = tid & 15, ty = tid >> 4;
    float acc[4][4];
#pragma unroll
    for (int i = 0; i < 4; i++)
#pragma unroll
        for (int j = 0; j < 4; j++) acc[i][j] = 0.f;

    int ar = tid >> 2, ac2 = (tid & 3) * 2;
    int br = tid >> 5, bc = tid & 31;

    for (int k0 = 0; k0 < K; k0 += 8) {
        float2 a2 = *reinterpret_cast<const float2*>(A + (size_t)(row0 + ar) * K + k0 + ac2);
        As[ac2][ar] = a2.x;
        As[ac2 + 1][ar] = a2.y;
        float w0 = (col0 + bc < N)      ? W[(size_t)(k0 + br) * N + col0 + bc]      : 0.f;
        float w1 = (col0 + bc + 32 < N) ? W[(size_t)(k0 + br) * N + col0 + bc + 32] : 0.f;
        Bs[br][bc] = w0;
        Bs[br][bc + 32] = w1;
        __syncthreads();
#pragma unroll
        for (int kk = 0; kk < 8; kk++) {
            float av[4], bv[4];
#pragma unroll
            for (int i = 0; i < 4; i++) av[i] = As[kk][ty * 4 + i];
#pragma unroll
            for (int j = 0; j < 4; j++) bv[j] = Bs[kk][tx * 4 + j];
#pragma unroll
            for (int i = 0; i < 4; i++)
#pragma unroll
                for (int j = 0; j < 4; j++) acc[i][j] += av[i] * bv[j];
        }
        __syncthreads();
    }
#pragma unroll
    for (int i = 0; i < 4; i++) {
        int r = row0 + ty * 4 + i;
        if (r >= M) continue;
#pragma unroll
        for (int j = 0; j < 4; j++) {
            int c = col0 + tx * 4 + j;
            if (c >= N) continue;
            float val = acc[i][j] + cadd;
            if (bias) val += bias[c];
            size_t idx = (size_t)r * N + c;
            if (flags & 1) val += C[idx];
            if (flags & 2) val = fmaxf(val, 0.f);
            C[idx] = val;
        }
    }
}

// ---------- LayerNorm (bf16 out) ----------
__global__ void ln_kernel(const float* __restrict__ x, bf16* __restrict__ out,
                          const float* __restrict__ g, const float* __restrict__ b, int rows)
{
    int warp = blockIdx.x * (blockDim.x >> 5) + (threadIdx.x >> 5);
    if (warp >= rows) return;
    int lane = threadIdx.x & 31;
    const float* xr = x + (size_t)warp * DD;
    float v[16], s1 = 0.f, s2 = 0.f;
#pragma unroll
    for (int i = 0; i < 16; i++) {
        float t = xr[i * 32 + lane];
        v[i] = t; s1 += t; s2 += t * t;
    }
#pragma unroll
    for (int o = 16; o; o >>= 1) {
        s1 += __shfl_xor_sync(0xffffffffu, s1, o);
        s2 += __shfl_xor_sync(0xffffffffu, s2, o);
    }
    float mu = s1 * (1.f / DD);
    float inv = rsqrtf(s2 * (1.f / DD) - mu * mu + 1e-5f);
    bf16* orow = out + (size_t)warp * DD;
#pragma unroll
    for (int i = 0; i < 16; i++) {
        int d = i * 32 + lane;
        orow[d] = __float2bfloat16((v[i] - mu) * inv * g[d] + b[d]);
    }
}

// ---------- pos-emb @ W_p ----------
__global__ void prep_p_kernel(const float* __restrict__ Wp, float* __restrict__ p)
{
    int jj = blockIdx.x;
    __shared__ float pe[DD];
    float pos = (float)(JJ - 1 - jj);
    for (int d = threadIdx.x; d < DD; d += 64) {
        int i = (d < 256) ? d : d - 256;
        float f = __expf(-(float)(2 * i) * (1.f / 512.f) * 9.210340371976184f);
        float a = pos * f;
        pe[d] = (d < 256) ? sinf(a) : cosf(a);
    }
    __syncthreads();
    int c = threadIdx.x;
    float acc = 0.f;
    for (int d = 0; d < DD; d++) acc += pe[d] * Wp[d * 64 + c];
    p[jj * 64 + c] = acc;
}

// ---------- attention: q/kv from fused QKV + memory kv ----------
__global__ void attn_kernel(const float* __restrict__ qkv, const float* __restrict__ kvm,
                            const float* __restrict__ p, const float* __restrict__ uu,
                            const float* __restrict__ vvec, bf16* __restrict__ av)
{
    int b = blockIdx.x, h = blockIdx.y;
    __shared__ float Ks[JJ][33];
    __shared__ float Vs[JJ][33];
    __shared__ float att[4][JJ];
    __shared__ float qsu[4][32];
    __shared__ float qsv[4][32];
    int tid = threadIdx.x;
    for (int idx = tid; idx < JJ * 32; idx += 128) {
        int j = idx >> 5, d = idx & 31;
        const float* row;
        if (j < MM)
            row = kvm + ((size_t)j * BB + b) * 128 + h * 32 + d;
        else
            row = qkv + ((size_t)(j - MM) * BB + b) * 192 + 64 + h * 32 + d;
        Ks[j][d] = row[0];
        Vs[j][d] = row[64];
    }
    __syncthreads();
    int warp = tid >> 5, lane = tid & 31;
    float ul = uu[h * 32 + lane], vl = vvec[h * 32 + lane];
    for (int i = warp; i < TT; i += 4) {
        float qv = qkv[((size_t)i * BB + b) * 192 + h * 32 + lane];
        qsu[warp][lane] = qv + ul;
        qsv[warp][lane] = qv + vl;
        __syncwarp();
        int jmax = i + MM;
        float sv[5], smax = -1e30f;
        int cnt = 0;
        for (int j = lane; j <= jmax; j += 32) {
            const float* prow = p + (size_t)(j + TT - 1 - i) * 64 + h * 32;
            float s = 0.f;
#pragma unroll
            for (int d = 0; d < 32; d++)
                s += qsu[warp][d] * Ks[j][d] + qsv[warp][d] * prow[d];
            s *= 0.1767766952966369f;
            sv[cnt++] = s;
            smax = fmaxf(smax, s);
        }
#pragma unroll
        for (int o = 16; o; o >>= 1) smax = fmaxf(smax, __shfl_xor_sync(0xffffffffu, smax, o));
        float sum = 0.f; cnt = 0;
        for (int j = lane; j <= jmax; j += 32) {
            float e = __expf(sv[cnt++] - smax);
            att[warp][j] = e;
            sum += e;
        }
#pragma unroll
        for (int o = 16; o; o >>= 1) sum += __shfl_xor_sync(0xffffffffu, sum, o);
        float inv = 1.f / sum;
        __syncwarp();
        float acc = 0.f;
        for (int j = 0; j <= jmax; j++) acc += att[warp][j] * Vs[j][lane];
        av[((size_t)i * BB + b) * 64 + h * 32 + lane] = __float2bfloat16(acc * inv);
        __syncwarp();
    }
}

// ---------- transpose+convert W[K,N] f32 -> [N,K] bf16 ----------
__global__ void tpose_kernel(const float* __restrict__ in, bf16* __restrict__ out, int K, int N)
{
    __shared__ float t[32][33];
    int k0 = blockIdx.y * 32, n0 = blockIdx.x * 32;
    int x = threadIdx.x, y = threadIdx.y;
    for (int i = y; i < 32; i += 8)
        t[i][x] = in[(size_t)(k0 + i) * N + n0 + x];
    __syncthreads();
    for (int i = y; i < 32; i += 8)
        out[(size_t)(n0 + i) * K + k0 + x] = __float2bfloat16(t[x][i]);
}

// ---------- batched transpose for the 12 gate matrices (512x512) ----------
__global__ void btpose_kernel(const float* __restrict__ g1, const float* __restrict__ g2,
                              bf16* __restrict__ o1, bf16* __restrict__ o2)
{
    __shared__ float t[32][33];
    int z = blockIdx.z;
    const float* in = (z < 6) ? (g1 + (size_t)z * DD * DD) : (g2 + (size_t)(z - 6) * DD * DD);
    bf16* out = (z < 6) ? (o1 + (size_t)z * DD * DD) : (o2 + (size_t)(z - 6) * DD * DD);
    int k0 = blockIdx.y * 32, n0 = blockIdx.x * 32;
    int x = threadIdx.x, y = threadIdx.y;
    for (int i = y; i < 32; i += 8)
        t[i][x] = in[(size_t)(k0 + i) * DD + n0 + x];
    __syncthreads();
    for (int i = y; i < 32; i += 8)
        out[(size_t)(n0 + i) * DD + k0 + x] = __float2bfloat16(t[x][i]);
}

// ---------- f32 -> bf16 ----------
__global__ void cvt_kernel(const float* __restrict__ in, bf16* __restrict__ out, int n4)
{
    int i = blockIdx.x * blockDim.x + threadIdx.x;
    if (i >= n4) return;
    float4 v = reinterpret_cast<const float4*>(in)[i];
    __nv_bfloat162* o = reinterpret_cast<__nv_bfloat162*>(out + (size_t)i * 4);
    o[0] = __floats2bfloat162_rn(v.x, v.y);
    o[1] = __floats2bfloat162_rn(v.z, v.w);
}

// ---------- mean pool (vectorized) ----------
__global__ void meanpool_kernel(const float4* __restrict__ in, float4* __restrict__ ts)
{
    int idx = blockIdx.x * blockDim.x + threadIdx.x;
    const int n4 = BB * DD / 4;
    if (idx >= n4) return;
    float4 s = make_float4(0.f, 0.f, 0.f, 0.f);
    for (int t = 0; t < TT; t++) {
        float4 v = in[(size_t)t * n4 + idx];
        s.x += v.x; s.y += v.y; s.z += v.z; s.w += v.w;
    }
    const float inv = 1.f / TT;
    s.x *= inv; s.y *= inv; s.z *= inv; s.w *= inv;
    ts[idx] = s;
}

// ---------- final head ----------
__global__ void final_kernel(const float* __restrict__ h3, const float* __restrict__ w,
                             const float* __restrict__ bb, float* __restrict__ out)
{
    int row = blockIdx.x * 4 + (threadIdx.x >> 5);
    int lane = threadIdx.x & 31;
    if (row >= BB) return;
    float s = 0.f;
    for (int k = lane; k < 300; k += 32) s += h3[(size_t)row * 300 + k] * w[k];
#pragma unroll
    for (int o = 16; o; o >>= 1) s += __shfl_xor_sync(0xffffffffu, s, o);
    if (lane == 0) out[row] = fmaxf(s + bb[0], 0.f);
}

// ---------- host ----------
static inline void launch_tc(const bf16* A0, const bf16* W0, int K0,
                             const bf16* A1, const bf16* W1, int K1,
                             int M, int N, int NT,
                             float* Cf, bf16* Cb,
                             const float* b1, const float* b2, float cadd,
                             const bf16* zpre, const float* aux, int mode)
{
    dim3 grid(N / NT, M / 128);
    if (NT == 128) {
        size_t dsz = 3 * (size_t)(128 + 128) * 144;
        bgemm<128><<<grid, 256, dsz>>>(A0, W0, K0, A1, W1, K1, N, Cf, Cb, b1, b2, cadd, zpre, aux, mode);
    } else {
        size_t dsz = 3 * (size_t)(128 + 64) * 144;
        bgemm<64><<<grid, 256, dsz>>>(A0, W0, K0, A1, W1, K1, N, Cf, Cb, b1, b2, cadd, zpre, aux, mode);
    }
}
static inline void launch_sgemm(const float* A, const float* W, float* C,
                                int M, int N, int K, const float* bias, float cadd, int flags)
{
    dim3 grid((N + 63) / 64, (M + 63) / 64);
    sgemm64_kernel<<<grid, 256>>>(A, W, C, M, N, K, bias, cadd, flags);
}
static inline void launch_tpose(const float* in, bf16* out, int K, int N)
{
    tpose_kernel<<<dim3(N / 32, K / 32), dim3(32, 8)>>>(in, out, K, N);
}

extern "C" void kernel_launch(void* const* d_in, const int* in_sizes, int n_in,
                              void* d_out, int out_size)
{
    const float* x      = (const float*)d_in[0];
    const float* action = (const float*)d_in[1];
    const float* memory = (const float*)d_in[2];
    const float* W_q    = (const float*)d_in[3];
    const float* W_kv   = (const float*)d_in[4];
    const float* W_p    = (const float*)d_in[5];
    const float* W_out  = (const float*)d_in[6];
    const float* u      = (const float*)d_in[7];
    const float* v      = (const float*)d_in[8];
    const float* ln1_g  = (const float*)d_in[9];
    const float* ln1_b  = (const float*)d_in[10];
    const float* ln2_g  = (const float*)d_in[11];
    const float* ln2_b  = (const float*)d_in[12];
    const float* ff_W1  = (const float*)d_in[13];
    const float* ff_b1  = (const float*)d_in[14];
    const float* ff_W2  = (const float*)d_in[15];
    const float* ff_b2  = (const float*)d_in[16];
    const float* g1W    = (const float*)d_in[17];
    const float* g1b    = (const float*)d_in[18];
    const float* g2W    = (const float*)d_in[19];
    const float* g2b    = (const float*)d_in[20];
    const float* d1W    = (const float*)d_in[21];
    const float* d1b    = (const float*)d_in[22];
    const float* d2W    = (const float*)d_in[23];
    const float* d2b    = (const float*)d_in[24];
    const float* d3W    = (const float*)d_in[25];
    const float* d3b    = (const float*)d_in[26];
    const float* d4W    = (const float*)d_in[27];
    const float* d4b    = (const float*)d_in[28];

    cudaFuncSetAttribute(bgemm<128>, cudaFuncAttributeMaxDynamicSharedMemorySize, 111000);
    cudaFuncSetAttribute(bgemm<64>,  cudaFuncAttributeMaxDynamicSharedMemorySize, 84000);

    float *B1, *B4, *QKV, *KVM, *P, *TS, *H1, *H2, *H3;
    bf16 *XB, *LNB, *YB, *RXB, *ZB, *SRCB, *FFHB, *AVB, *MEMB;
    bf16 *WQKVT, *WOUTT, *G1T, *G2T, *FF1T, *FF2T;
    cudaGetSymbolAddress((void**)&B1,   g_B1);
    cudaGetSymbolAddress((void**)&B4,   g_B4);
    cudaGetSymbolAddress((void**)&QKV,  g_qkv);
    cudaGetSymbolAddress((void**)&KVM,  g_kvm);
    cudaGetSymbolAddress((void**)&P,    g_p);
    cudaGetSymbolAddress((void**)&TS,   g_ts);
    cudaGetSymbolAddress((void**)&H1,   g_h1);
    cudaGetSymbolAddress((void**)&H2,   g_h2);
    cudaGetSymbolAddress((void**)&H3,   g_h3);
    cudaGetSymbolAddress((void**)&XB,   gb_x);
    cudaGetSymbolAddress((void**)&LNB,  gb_ln);
    cudaGetSymbolAddress((void**)&YB,   gb_y);
    cudaGetSymbolAddress((void**)&RXB,  gb_rx);
    cudaGetSymbolAddress((void**)&ZB,   gb_z);
    cudaGetSymbolAddress((void**)&SRCB, gb_src);
    cudaGetSymbolAddress((void**)&FFHB, gb_ffh);
    cudaGetSymbolAddress((void**)&AVB,  gb_av);
    cudaGetSymbolAddress((void**)&MEMB, gb_mem);
    cudaGetSymbolAddress((void**)&WQKVT,gb_wqkv);
    cudaGetSymbolAddress((void**)&WOUTT,gb_wout);
    cudaGetSymbolAddress((void**)&G1T,  gb_g1);
    cudaGetSymbolAddress((void**)&G2T,  gb_g2);
    cudaGetSymbolAddress((void**)&FF1T, gb_ff1);
    cudaGetSymbolAddress((void**)&FF2T, gb_ff2);

    const size_t SZ = (size_t)DD * DD;

    // weight prep: gates batched; Wq^T into rows 0-63 and Wkv^T into rows 64-191 of WQKVT
    btpose_kernel<<<dim3(16, 16, 12), dim3(32, 8)>>>(g1W, g2W, G1T, G2T);
    launch_tpose(W_q,   WQKVT,            DD, 64);
    launch_tpose(W_kv,  WQKVT + 64 * DD,  DD, 128);
    launch_tpose(W_out, WOUTT, 64, DD);
    launch_tpose(ff_W1, FF1T, DD, DFF);
    launch_tpose(ff_W2, FF2T, DFF, DD);

    // activation converts
    cvt_kernel<<<(NROW * DD / 4 + 255) / 256, 256>>>(x, XB, NROW * DD / 4);
    cvt_kernel<<<(MM * BB * DD / 4 + 255) / 256, 256>>>(memory, MEMB, MM * BB * DD / 4);

    // pos emb
    prep_p_kernel<<<JJ, 64>>>(W_p, P);

    // LN1 -> LNB (bf16)
    ln_kernel<<<NROW / 8, 256>>>(x, LNB, ln1_g, ln1_b, NROW);

    // fused qkv = LN1 @ [Wq|Wkv] (f32 out, N=192)
    launch_tc(LNB, WQKVT, DD, 0, 0, 0, NROW, 192, 64, QKV, 0, 0, 0, 0.f, 0, 0, 0);

    // memory kv = memory @ Wkv (f32 out)
    launch_tc(MEMB, WQKVT + 64 * DD, DD, 0, 0, 0, MM * BB, 128, 128, KVM, 0, 0, 0, 0.f, 0, 0, 0);

    // attention -> AVB (bf16)
    attn_kernel<<<dim3(BB, HH), 128>>>(QKV, KVM, P, u, v, AVB);

    // y = av @ W_out -> YB (bf16)
    launch_tc(AVB, WOUTT, 64, 0, 0, 0, NROW, DD, 128, 0, YB, 0, 0, 0.f, 0, 0, 2);

    // gate 1: src = g(x, y)
    launch_tc(YB, G1T + 0 * SZ, DD, XB, G1T + 1 * SZ, DD, NROW, DD, 128,
              0, RXB, g1b + 0 * DD, g1b + 1 * DD, 0.f, 0, x, 4);                 // r*x (bf16)
    launch_tc(YB, G1T + 2 * SZ, DD, XB, G1T + 3 * SZ, DD, NROW, DD, 128,
              0, ZB, g1b + 2 * DD, g1b + 3 * DD, -BG, 0, 0, 2);                  // z_pre (bf16)
    launch_tc(YB, G1T + 4 * SZ, DD, RXB, G1T + 5 * SZ, DD, NROW, DD, 128,
              B4, SRCB, g1b + 4 * DD, g1b + 5 * DD, 0.f, ZB, x, 5);              // src

    // ff = relu(LN2(src)@W1+b1)@W2+b2 -> XB (x no longer needed)
    ln_kernel<<<NROW / 8, 256>>>(B4, LNB, ln2_g, ln2_b, NROW);
    launch_tc(LNB, FF1T, DD, 0, 0, 0, NROW, DFF, 64, 0, FFHB, ff_b1, 0, 0.f, 0, 0, 3);
    launch_tc(FFHB, FF2T, DFF, 0, 0, 0, NROW, DD, 128, 0, XB, ff_b2, 0, 0.f, 0, 0, 2);

    // gate 2: out = g(src, ff) -> B1 (f32)
    launch_tc(XB, G2T + 0 * SZ, DD, SRCB, G2T + 1 * SZ, DD, NROW, DD, 128,
              0, RXB, g2b + 0 * DD, g2b + 1 * DD, 0.f, 0, B4, 4);
    launch_tc(XB, G2T + 2 * SZ, DD, SRCB, G2T + 3 * SZ, DD, NROW, DD, 128,
              0, ZB, g2b + 2 * DD, g2b + 3 * DD, -BG, 0, 0, 2);
    launch_tc(XB, G2T + 4 * SZ, DD, RXB, G2T + 5 * SZ, DD, NROW, DD, 128,
              B1, 0, g2b + 4 * DD, g2b + 5 * DD, 0.f, ZB, B4, 5);

    // mean pool
    meanpool_kernel<<<(BB * DD / 4 + 255) / 256, 256>>>((const float4*)B1, (float4*)TS);

    // critic head (exact fp32)
    launch_sgemm(TS, d1W, H1, BB, 1024, DD, d1b, 0.f, 2);
    launch_sgemm(H1, d2W, H2, BB, 512, 1024, nullptr, 0.f, 0);
    launch_sgemm(action, d2W + (size_t)1024 * 512, H2, BB, 512, ACT, d2b, 0.f, 3);
    launch_sgemm(H2, d3W, H3, BB, 300, DD, d3b, 0.f, 2);
    final_kernel<<<BB / 4, 128>>>(H3, d4W, d4b, (float*)d_out);
}